// round 9
// baseline (speedup 1.0000x reference)
#include <cuda_runtime.h>
#include <cuda_bf16.h>
#include <cuda_fp16.h>
#include <cstdint>

// ============================================================================
// IsingRBM: psi[m] = prod_h cos(bias[h] + (x@W1)[m,h] + 0.5 * x^T W2[h] x)
// R9: FP8 e4m3 mma.sync.m16n8k32 (sm_89-baseline PTX).
//  * B = packed symmetric-triangle weights, pre-scaled by S=2^14, stored e4m3:
//    chunk = 128h x 64k bytes = 8 KB (half of bf16) -> cp.async + LDSM halve.
//  * B fragments via the b16 ldmatrix trick: view pairs of e4m3 as b16; the
//    m16n8k16-bf16 fragment mapping then yields exactly the e4m3 k32 fragment.
//    SMEM rows 64 B, SW64 swizzle (conflict-free for ldmatrix + cp.async).
//  * A (x_i*x_j products) built per-warp in registers: f16 base pairs * f16
//    broadcast scale -> cvt.rn.satfinite.e4m3x2.f16x2 -> pack.
//  * Skeleton = R4 (bench-best): 2 CTAs x 256 thr, M-tile 64, 2Mx4N warps,
//    3 B-buffers, per-chunk barrier. Prep = R7 style (CTA per h, smem stage).
//  * Epilogue: a = bias + acc * (0.5 / S).
// Schedule (regions A..E over 41 chunks / 164 k16-blocks) unchanged.
// ============================================================================

static constexpr int kV = 64;
static constexpr int kH = 128;
static constexpr int kMTile = 64;
static constexpr int kChunks = 41;
static constexpr int kChunkBytes = kH * kV;       // 8192 (e4m3)
static constexpr int kThreads = 256;
static constexpr float kS    = 16384.0f;          // weight pre-scale (2^14)
static constexpr float kInvS = 0.5f / 16384.0f;   // epilogue factor

// smem layout (bytes, relative to 1024-aligned base)
static constexpr int SM_BIAS = 0;                   // 128 f32 = 512
static constexpr int SM_PART = 512;                 // 64*4 f32 = 1024
static constexpr int SM_XQ   = 1536;                // 64j*16grp*4t u32 = 16384
static constexpr int SM_B    = 18432;               // 3 * 8192 (1024-aligned)
static constexpr int SM_XF   = SM_B + 2 * kChunkBytes;  // x f16 tile, overlay buf2
static constexpr int SM_END  = SM_B + 3 * kChunkBytes;  // 43008
static constexpr int SMEM_TOTAL = SM_END + 1024;    // 44032; x2 CTAs ok

// Packed, scaled e4m3 B operand: [chunk][h][64] bytes.
__device__ __align__(16) unsigned char g_wb[kChunks * kChunkBytes];

// ---------------------------------------------------------------------------
// helpers
// ---------------------------------------------------------------------------
__device__ __forceinline__ uint32_t smem_u32(const void* p) {
    uint32_t a;
    asm("{ .reg .u64 t; cvta.to.shared.u64 t, %1; cvt.u32.u64 %0, t; }"
        : "=r"(a) : "l"(p));
    return a;
}

#define SW64(o) ((o) ^ (((o) >> 3) & 0x30))

// f32 pair -> e4m3x2 (b16), a->high byte, b->low byte handled by operand swap
#define CVT_E4X2_F32(d, lo, hi) \
    asm("cvt.rn.satfinite.e4m3x2.f32 %0, %2, %1;" : "=h"(d) : "f"(lo), "f"(hi))

// f16x2 -> e4m3x2 (elementwise, lo->byte0)
#define CVT_E4X2_F16X2(d, a) \
    asm("cvt.rn.satfinite.e4m3x2.f16x2 %0, %1;" : "=h"(d) : "r"(a))

#define PACK16X2(d, lo, hi) \
    asm("mov.b32 %0, {%1, %2};" : "=r"(d) : "h"(lo), "h"(hi))

#define HMUL2F(d, a, b) \
    asm("mul.rn.f16x2 %0, %1, %2;" : "=r"(d) : "r"(a), "r"(b))

#define LDSM_X4(r0, r1, r2, r3, addr) \
    asm volatile("ldmatrix.sync.aligned.m8n8.x4.shared.b16 {%0,%1,%2,%3}, [%4];" \
        : "=r"(r0), "=r"(r1), "=r"(r2), "=r"(r3) : "r"(addr))

#define MMA_FP8(d, a0, a1, a2, a3, b0, b1) \
    asm volatile("mma.sync.aligned.m16n8k32.row.col.f32.e4m3.e4m3.f32 " \
        "{%0,%1,%2,%3}, {%4,%5,%6,%7}, {%8,%9}, {%0,%1,%2,%3};" \
        : "+f"((d)[0]), "+f"((d)[1]), "+f"((d)[2]), "+f"((d)[3]) \
        : "r"(a0), "r"(a1), "r"(a2), "r"(a3), "r"(b0), "r"(b1))

#define CP_ASYNC16(smem, gmem) \
    asm volatile("cp.async.cg.shared.global [%0], [%1], 16;" \
        :: "r"(smem), "l"(gmem) : "memory")
#define CP_COMMIT() asm volatile("cp.async.commit_group;" ::: "memory")
#define CP_WAIT1()  asm volatile("cp.async.wait_group 1;" ::: "memory")

__device__ __forceinline__ float cos_poly(float a) {
    // |a| < 0.1 guaranteed by problem statistics; deg-8 Taylor, err < 1e-12
    float t = a * a;
    return 1.0f + t * (-0.5f + t * (4.16666667e-2f +
               t * (-1.38888889e-3f + t * 2.48015873e-5f)));
}

// block schedule decode — used ONLY by the one-shot prep kernel
__device__ __forceinline__ int decode_i(int b) {
    if (b < 64)  return b >> 2;
    if (b < 112) return 16 + (b - 64) / 3;
    if (b < 144) return 32 + ((b - 112) >> 1);
    if (b < 160) return 48 + (b - 144);
    return 64;
}
__device__ __forceinline__ int decode_kbf(int b) {
    if (b < 64)  return b & 3;
    if (b < 112) return 1 + (b - 64) % 3;
    if (b < 144) return 2 + ((b - 112) & 1);
    if (b < 160) return 3;
    return b - 160;
}

// ---------------------------------------------------------------------------
// prep: one CTA per h. Stage W2[h] in smem, emit scaled e4m3 packed rows.
// ---------------------------------------------------------------------------
__global__ void __launch_bounds__(256) prep_kernel(const float* __restrict__ w2,
                                                   const float* __restrict__ w1) {
    __shared__ float sw[4096];
    const int h = blockIdx.x;
    const float4* src = reinterpret_cast<const float4*>(w2 + (size_t)h * 4096);
    #pragma unroll
    for (int e = threadIdx.x; e < 1024; e += 256)
        reinterpret_cast<float4*>(sw)[e] = src[e];
    __syncthreads();

    // 164 blocks * 4 quads of 4 cols = 656 u32 outputs (4 e4m3 each) for this h
    for (int idx = threadIdx.x; idx < 656; idx += 256) {
        int b    = idx >> 2;
        int part = idx & 3;
        int i    = decode_i(b);
        int kbf  = decode_kbf(b);
        int j0   = kbf * 16 + part * 4;
        float v[4];
        #pragma unroll
        for (int q = 0; q < 4; q++) {
            int j = j0 + q;
            float w;
            if (i == 64)     w = 2.0f * w1[j * kH + h];
            else if (j > i)  w = sw[i * 64 + j] + sw[j * 64 + i];
            else if (j == i) w = sw[i * 64 + j];
            else             w = 0.0f;
            v[q] = w * kS;
        }
        unsigned short c0, c1;
        CVT_E4X2_F32(c0, v[0], v[1]);
        CVT_E4X2_F32(c1, v[2], v[3]);
        uint32_t packed;
        PACK16X2(packed, c0, c1);
        int c   = b >> 2;
        int col = (b & 3) * 16 + part * 4;
        reinterpret_cast<uint32_t*>(g_wb)[c * 2048 + h * 16 + (col >> 2)] = packed;
    }
}

// ---------------------------------------------------------------------------
// A-reg builder: two f16x2 j-pairs * broadcast scale -> 4 packed e4m3
// ---------------------------------------------------------------------------
__device__ __forceinline__ uint32_t a_pack(uint32_t p01, uint32_t p23, uint32_t s) {
    uint32_t m0, m1;
    HMUL2F(m0, p01, s);
    HMUL2F(m1, p23, s);
    unsigned short c0, c1;
    CVT_E4X2_F16X2(c0, m0);
    CVT_E4X2_F16X2(c1, m1);
    uint32_t r;
    PACK16X2(r, c0, c1);
    return r;
}

// ---------------------------------------------------------------------------
// chunk body: kbf + i-delta patterns compile-time. Per ks (k32 step):
// 2 LDS.128 scales + 2 LDSM.x4 (B) + per mb: 4 a_pack + 4 MMA.
// ---------------------------------------------------------------------------
template<int K0, int K1, int K2, int K3, int D0, int D1, int D2, int D3, bool LIN>
__device__ __forceinline__ void do_chunk(
    uint32_t bb, const uint32_t* __restrict__ boff,
    const uint32_t (&xb)[2][4][4],
    const uint32_t* __restrict__ xq4, int ibase,
    float (&acc)[2][4][4])
{
    const int KF[4] = {K0, K1, K2, K3};
    const int DI[4] = {D0, D1, D2, D3};
    #pragma unroll
    for (int ks = 0; ks < 2; ks++) {
        uint32_t svA[4], svB[4];
        if (LIN) {
            #pragma unroll
            for (int t = 0; t < 4; t++) { svA[t] = 0x3C003C00u; svB[t] = 0x3C003C00u; }
        } else {
            uint4 sa = *reinterpret_cast<const uint4*>(
                xq4 + (ibase + DI[2 * ks]) * 64);
            uint4 sb2 = *reinterpret_cast<const uint4*>(
                xq4 + (ibase + DI[2 * ks + 1]) * 64);
            svA[0] = sa.x;  svA[1] = sa.y;  svA[2] = sa.z;  svA[3] = sa.w;
            svB[0] = sb2.x; svB[1] = sb2.y; svB[2] = sb2.z; svB[3] = sb2.w;
        }
        uint32_t bf[4][2];
        LDSM_X4(bf[0][0], bf[0][1], bf[1][0], bf[1][1], bb + boff[ks * 2 + 0]);
        LDSM_X4(bf[2][0], bf[2][1], bf[3][0], bf[3][1], bb + boff[ks * 2 + 1]);
        #pragma unroll
        for (int mb = 0; mb < 2; mb++) {
            const int ka = KF[2 * ks], kb2 = KF[2 * ks + 1];
            uint32_t a0 = a_pack(xb[mb][ka][0],  xb[mb][ka][1],  svA[2 * mb]);
            uint32_t a1 = a_pack(xb[mb][ka][2],  xb[mb][ka][3],  svA[2 * mb + 1]);
            uint32_t a2 = a_pack(xb[mb][kb2][0], xb[mb][kb2][1], svB[2 * mb]);
            uint32_t a3 = a_pack(xb[mb][kb2][2], xb[mb][kb2][3], svB[2 * mb + 1]);
            #pragma unroll
            for (int nb = 0; nb < 4; nb++)
                MMA_FP8(acc[mb][nb], a0, a1, a2, a3, bf[nb][0], bf[nb][1]);
        }
    }
}

// ---------------------------------------------------------------------------
// main fused kernel: 64-row M-tile per CTA, H=128 as N, 8 warps (2M x 4N),
// 2 CTAs per SM, 3 B-buffers, barrier per chunk (R4 skeleton)
// ---------------------------------------------------------------------------
__global__ void __launch_bounds__(kThreads, 2)
rbm_main_kernel(const float* __restrict__ x,
                const float* __restrict__ bias,
                float* __restrict__ out) {
    extern __shared__ char smem_raw[];
    char* sm = (char*)((((uintptr_t)smem_raw) + 1023) & ~(uintptr_t)1023);
    const uint32_t sb = smem_u32(sm);
    const int tid = threadIdx.x;
    const int l   = tid & 31;
    const int w   = tid >> 5;
    const int g   = l >> 2;
    const int t4  = l & 3;
    const int wm  = (w >> 2) * 32;     // warp M offset (0,32)
    const int wn  = (w & 3) * 32;      // warp N offset (0,32,64,96)
    const int m0  = blockIdx.x * kMTile;

    float*    sbias = (float*)(sm + SM_BIAS);
    float*    spart = (float*)(sm + SM_PART);     // [m][4 wn-groups]
    uint32_t* xq    = (uint32_t*)(sm + SM_XQ);    // [j][16 grp][4 t] f16x2

    if (tid < kH) sbias[tid] = bias[tid];

    // --- x f16 tile [m][j], plain 128B rows (A-base source; overlay buf2) ---
    {
        const float4* x4 = (const float4*)(x + (size_t)m0 * kV);
        #pragma unroll
        for (int e = tid; e < kMTile * 16; e += kThreads) {   // 64 rows * 16 float4
            int r = e >> 4, q = e & 15;
            float4 f = x4[e];
            __half2 h01 = __floats2half2_rn(f.x, f.y);
            __half2 h23 = __floats2half2_rn(f.z, f.w);
            uint2 u;
            u.x = *reinterpret_cast<uint32_t*>(&h01);
            u.y = *reinterpret_cast<uint32_t*>(&h23);
            *(uint2*)(sm + SM_XF + r * 128 + q * 8) = u;
        }
    }
    // --- xq[j][grp][t] = f16x2 broadcast of x[m0 + (grp>>3)*32 + (grp&7) + 8t][j]
    #pragma unroll
    for (int e = tid; e < kV * 16 * 4; e += kThreads) {   // 4096 entries
        int j   = e >> 6;
        int grp = (e >> 2) & 15;
        int t   = e & 3;
        int m   = (grp >> 3) * 32 + (grp & 7) + 8 * t;
        float v = x[(size_t)(m0 + m) * kV + j];
        __half2 hh = __floats2half2_rn(v, v);
        xq[e] = *reinterpret_cast<uint32_t*>(&hh);
    }

    // --- cp.async offsets (hoisted): 2 x 16B per thread per chunk ---
    uint32_t cp_raw[2], cp_dst[2];
    #pragma unroll
    for (int p = 0; p < 2; p++) {
        int cg = tid + p * kThreads;                 // 512 x 16B = 8192 B
        cp_raw[p] = (uint32_t)((cg >> 2) * 64 + (cg & 3) * 16);
        cp_dst[p] = SW64(cp_raw[p]);
    }
    const char* gw = (const char*)g_wb;
    #define ISSUE_CHUNK(c, buf) do {                                          \
        const char* _src = gw + (size_t)(c) * kChunkBytes;                    \
        uint32_t _dst = sb + SM_B + (uint32_t)(buf) * kChunkBytes;            \
        CP_ASYNC16(_dst + cp_dst[0], _src + cp_raw[0]);                       \
        CP_ASYNC16(_dst + cp_dst[1], _src + cp_raw[1]);                       \
    } while (0)

    ISSUE_CHUNK(0, 0); CP_COMMIT();
    ISSUE_CHUNK(1, 1); CP_COMMIT();

    __syncthreads();   // x tiles + bias ready

    // --- A-base f16x2 pairs (warp's 32x64 x-tile rows) in registers ---
    // xb[mb][kbf][0,1] = row (wm+16mb+g)   j = kbf*16 + t4*4 + {0..3}
    // xb[mb][kbf][2,3] = row (wm+16mb+g+8)
    uint32_t xb[2][4][4];
    #pragma unroll
    for (int mb = 0; mb < 2; mb++)
    #pragma unroll
    for (int kbf = 0; kbf < 4; kbf++) {
        int rlo = wm + 16 * mb + g;
        uint2 ulo = *(const uint2*)(sm + SM_XF + rlo * 128 + kbf * 32 + t4 * 8);
        uint2 uhi = *(const uint2*)(sm + SM_XF + (rlo + 8) * 128 + kbf * 32 + t4 * 8);
        xb[mb][kbf][0] = ulo.x; xb[mb][kbf][1] = ulo.y;
        xb[mb][kbf][2] = uhi.x; xb[mb][kbf][3] = uhi.y;
    }

    // --- B ldmatrix offsets (b16 trick): per (ks, n-pair p) one LDSM.x4 ---
    // lane q=l>>3, rr=l&7: row = wn + p*16 + (q>>1)*8 + rr (n dim),
    // byte = ks*32 + (q&1)*16 (k dim). 64B rows, SW64.
    uint32_t boff[4];
    {
        int q = l >> 3, rr = l & 7;
        #pragma unroll
        for (int ks = 0; ks < 2; ks++)
        #pragma unroll
        for (int p = 0; p < 2; p++) {
            uint32_t off = (uint32_t)((wn + p * 16 + (q >> 1) * 8 + rr) * 64
                                      + ks * 32 + (q & 1) * 16);
            boff[ks * 2 + p] = SW64(off);
        }
    }

    float acc[2][4][4];
    #pragma unroll
    for (int a = 0; a < 2; a++)
    #pragma unroll
    for (int b = 0; b < 4; b++)
    #pragma unroll
    for (int c = 0; c < 4; c++) acc[a][b][c] = 0.0f;

    const int rb0 = wm + g;
    const uint32_t* xq4 = xq + ((wm >> 2) + g) * 4;   // grp = (wm>>2)+g

    // pipeline (R4): wait chunk c, release buffer (c+2)%3, prefetch c+2, body
    int c = 0;
    #define PIPE(BODY) do {                                                   \
        CP_WAIT1();                                                           \
        __syncthreads();                                                      \
        if (c + 2 < kChunks) { ISSUE_CHUNK(c + 2, (c + 2) % 3); }             \
        CP_COMMIT();                                                          \
        uint32_t bb = sb + SM_B + (uint32_t)(c % 3) * kChunkBytes;            \
        BODY;                                                                 \
        c++;                                                                  \
    } while (0)

    // Region A: i = c, kbf 0..3
    #pragma unroll 1
    for (int cc = 0; cc < 16; cc++) {
        PIPE((do_chunk<0,1,2,3, 0,0,0,0, false>(bb, boff, xb, xq4, cc, acc)));
    }
    // Region B: 3-chunk period, i 16..31
    int I = 16;
    #pragma unroll 1
    for (int r = 0; r < 4; r++) {
        PIPE((do_chunk<1,2,3,1, 0,0,0,1, false>(bb, boff, xb, xq4, I,     acc)));
        PIPE((do_chunk<2,3,1,2, 0,0,1,1, false>(bb, boff, xb, xq4, I + 1, acc)));
        PIPE((do_chunk<3,1,2,3, 0,1,1,1, false>(bb, boff, xb, xq4, I + 2, acc)));
        I += 4;
    }
    // Region C: i 32..47
    #pragma unroll 1
    for (int r = 0; r < 8; r++) {
        PIPE((do_chunk<2,3,2,3, 0,0,1,1, false>(bb, boff, xb, xq4, I, acc)));
        I += 2;
    }
    // Region D: i 48..63
    #pragma unroll 1
    for (int r = 0; r < 4; r++) {
        PIPE((do_chunk<3,3,3,3, 0,1,2,3, false>(bb, boff, xb, xq4, I, acc)));
        I += 4;
    }
    // Region E: linear term (scale = 1.0 f16)
    PIPE((do_chunk<0,1,2,3, 0,0,0,0, true>(bb, boff, xb, xq4, 0, acc)));

    // --- epilogue: a = bias + (0.5/S)*acc; psi = prod cos(a) ---
    #pragma unroll
    for (int mb = 0; mb < 2; mb++) {
        float p0 = 1.0f, p1 = 1.0f;
        #pragma unroll
        for (int nb = 0; nb < 4; nb++) {
            int col = wn + nb * 8 + 2 * t4;
            #pragma unroll
            for (int cc = 0; cc < 2; cc++) {
                float bv = sbias[col + cc];
                p0 *= cos_poly(bv + kInvS * acc[mb][nb][cc]);       // row g
                p1 *= cos_poly(bv + kInvS * acc[mb][nb][2 + cc]);   // row g+8
            }
        }
        p0 *= __shfl_xor_sync(0xFFFFFFFFu, p0, 1);
        p0 *= __shfl_xor_sync(0xFFFFFFFFu, p0, 2);
        p1 *= __shfl_xor_sync(0xFFFFFFFFu, p1, 1);
        p1 *= __shfl_xor_sync(0xFFFFFFFFu, p1, 2);
        if (t4 == 0) {
            spart[(rb0 + 16 * mb) * 4 + (w & 3)]     = p0;
            spart[(rb0 + 16 * mb + 8) * 4 + (w & 3)] = p1;
        }
    }
    __syncthreads();
    if (tid < kMTile) {
        out[m0 + tid] = spart[tid * 4 + 0] * spart[tid * 4 + 1]
                      * spart[tid * 4 + 2] * spart[tid * 4 + 3];
    }
}

// ---------------------------------------------------------------------------
// launch
// ---------------------------------------------------------------------------
extern "C" void kernel_launch(void* const* d_in, const int* in_sizes, int n_in,
                              void* d_out, int out_size) {
    const float* x    = (const float*)d_in[0];   // (16384, 64)
    const float* w1   = (const float*)d_in[1];   // (64, 128)
    const float* w2   = (const float*)d_in[2];   // (128, 64, 64)
    const float* bias = (const float*)d_in[3];   // (128,)
    float* out = (float*)d_out;                  // (16384,)

    cudaFuncSetAttribute(rbm_main_kernel,
                         cudaFuncAttributeMaxDynamicSharedMemorySize, SMEM_TOTAL);

    prep_kernel<<<kH, 256>>>(w2, w1);            // one CTA per h
    rbm_main_kernel<<<16384 / kMTile, kThreads, SMEM_TOTAL>>>(x, bias, out);
}

// round 10
// speedup vs baseline: 1.3647x; 1.3647x over previous
#include <cuda_runtime.h>
#include <cuda_bf16.h>
#include <cstdint>

// ============================================================================
// IsingRBM: psi[m] = prod_h cos(bias[h] + (x@W1)[m,h] + 0.5 * x^T W2[h] x)
// mma.sync.m16n8k16 bf16 (compute_103 baseline PTX; tcgen05 unavailable).
//
// R10: 8-granular symmetric packing. Row i of the folded upper triangle
// starts at j = 8*floor(i/8) (octet-aligned), so K = 2368 = 296 octet-halves
// = 148 k16-blocks = 37 chunks of 64 (vs 41 at 16-alignment: -9.8% work on
// MMA + LDSM + cp.async + barriers). A k16 block may straddle two rows with
// different scales; the A fragment splits k into octets per register pair,
// so per-half scales cost the same 4 HMUL2.
// The entire schedule derives from ONE constexpr half_desc(H) used by both
// prep and main (consistency by construction); chunks are template-unrolled
// so scale offsets and A-register indices are immediates.
// Skeleton: R6 main (512 thr, 1 CTA/SM, M-tile 128, 4Mx4N warps, 8 B-buffers,
// quad barriers) + R7 prep (one CTA per h, W2[h] staged in smem).
// ============================================================================

static constexpr int kV = 64;
static constexpr int kH = 128;
static constexpr int kMTile = 128;
static constexpr int kChunks = 37;
static constexpr int kChunkBytes = kH * kV * 2;   // 16384
static constexpr int kThreads = 512;

// smem layout (bytes, relative to 1024-aligned base)
static constexpr int SM_BIAS = 0;                  // 128 f32 = 512
static constexpr int SM_PART = 512;                // 128*4 f32 = 2048
static constexpr int SM_XQ   = 2560;               // 64 j * 32 grp * 4 t u32 = 32768
static constexpr int SM_B    = 35840;              // 8 * 16384, 1024-aligned
static constexpr int SM_XT   = SM_B + 4 * kChunkBytes;      // overlay on buf 4
static constexpr int SM_END  = SM_B + 8 * kChunkBytes;      // 166912
static constexpr int SMEM_TOTAL = SM_END + 1024;   // 167936 < 227 KB

// Packed B operand: [chunk][h][64] bf16.
__device__ __align__(16) __nv_bfloat16 g_wb[kChunks * kH * kV];

// ---------------------------------------------------------------------------
// schedule: half H (octet of K) -> (row i, j-octet jo).  i == 64 => linear.
// Group a = i>>3 holds rows 8a..8a+7, each covering octets a..7.
// ---------------------------------------------------------------------------
struct HD { int i; int jo; };
__host__ __device__ constexpr HD half_desc(int H) {
    if (H >= 288) return HD{64, H - 288};          // linear term (scale = 1)
    int a = 0, gs = 0;
    while (gs + 8 * (8 - a) <= H) { gs += 8 * (8 - a); ++a; }
    int rem = H - gs, len = 8 - a;
    return HD{8 * a + rem / len, a + rem % len};
}

// ---------------------------------------------------------------------------
// helpers
// ---------------------------------------------------------------------------
__device__ __forceinline__ uint32_t smem_u32(const void* p) {
    uint32_t a;
    asm("{ .reg .u64 t; cvta.to.shared.u64 t, %1; cvt.u32.u64 %0, t; }"
        : "=r"(a) : "l"(p));
    return a;
}

#define SW128(o) ((o) ^ (((o) >> 3) & 0x70))

#define CVT_BF16X2(result, a, b) \
    asm("cvt.rn.bf16x2.f32 %0, %1, %2;" : "=r"(result) : "f"(b), "f"(a))

#define HMUL2(d, a, b) \
    asm("mul.rn.bf16x2 %0, %1, %2;" : "=r"(d) : "r"(a), "r"(b))

#define LDSM_X4(r0, r1, r2, r3, addr) \
    asm volatile("ldmatrix.sync.aligned.m8n8.x4.shared.b16 {%0,%1,%2,%3}, [%4];" \
        : "=r"(r0), "=r"(r1), "=r"(r2), "=r"(r3) : "r"(addr))

#define MMA16816(d, a0, a1, a2, a3, b0, b1) \
    asm volatile("mma.sync.aligned.m16n8k16.row.col.f32.bf16.bf16.f32 " \
        "{%0,%1,%2,%3}, {%4,%5,%6,%7}, {%8,%9}, {%0,%1,%2,%3};" \
        : "+f"((d)[0]), "+f"((d)[1]), "+f"((d)[2]), "+f"((d)[3]) \
        : "r"(a0), "r"(a1), "r"(a2), "r"(a3), "r"(b0), "r"(b1))

#define CP_ASYNC16(smem, gmem) \
    asm volatile("cp.async.cg.shared.global [%0], [%1], 16;" \
        :: "r"(smem), "l"(gmem) : "memory")
#define CP_COMMIT() asm volatile("cp.async.commit_group;" ::: "memory")
#define CP_WAIT4()  asm volatile("cp.async.wait_group 4;" ::: "memory")

__device__ __forceinline__ float cos_poly(float a) {
    // |a| < 0.1 guaranteed by problem statistics; deg-8 Taylor, err < 1e-12
    float t = a * a;
    return 1.0f + t * (-0.5f + t * (4.16666667e-2f +
               t * (-1.38888889e-3f + t * 2.48015873e-5f)));
}

// ---------------------------------------------------------------------------
// prep (R7 style): one CTA per h. Stage W2[h] in smem (coalesced), emit the
// packed bf16 row for every column of every chunk via half_desc.
// ---------------------------------------------------------------------------
__global__ void __launch_bounds__(256) prep_kernel(const float* __restrict__ w2,
                                                   const float* __restrict__ w1) {
    __shared__ float sw[4096];
    const int h = blockIdx.x;
    const float4* src = reinterpret_cast<const float4*>(w2 + (size_t)h * 4096);
    #pragma unroll
    for (int e = threadIdx.x; e < 1024; e += 256)
        reinterpret_cast<float4*>(sw)[e] = src[e];
    __syncthreads();

    // 37 chunks * 16 col-quads = 592 uint2 outputs for this h
    for (int idx = threadIdx.x; idx < kChunks * 16; idx += 256) {
        int c    = idx >> 4;
        int colq = (idx & 15) * 4;
        float v[4];
        #pragma unroll
        for (int q = 0; q < 4; q++) {
            int col = colq + q;
            HD hd = half_desc(c * 8 + (col >> 3));
            int j = hd.jo * 8 + (col & 7);
            if (hd.i == 64)     v[q] = 2.0f * w1[j * kH + h];
            else if (j > hd.i)  v[q] = sw[hd.i * 64 + j] + sw[j * 64 + hd.i];
            else if (j == hd.i) v[q] = sw[hd.i * 64 + j];
            else                v[q] = 0.0f;   // octet padding below diagonal
        }
        uint32_t lo, hi;
        CVT_BF16X2(lo, v[0], v[1]);
        CVT_BF16X2(hi, v[2], v[3]);
        reinterpret_cast<uint2*>(g_wb)[c * 2048 + h * 16 + (colq >> 2)] =
            make_uint2(lo, hi);
    }
}

// ---------------------------------------------------------------------------
// cp.async issue (2 x 16B per thread per chunk; 512 thr -> 16 KB)
// ---------------------------------------------------------------------------
__device__ __forceinline__ void issue_chunk(int c, uint32_t sb,
    const uint32_t (&cp_raw)[2], const uint32_t (&cp_dst)[2]) {
    const char* src = (const char*)g_wb + (size_t)c * kChunkBytes;
    uint32_t dst = sb + SM_B + (uint32_t)(c & 7) * kChunkBytes;
    CP_ASYNC16(dst + cp_dst[0], src + cp_raw[0]);
    CP_ASYNC16(dst + cp_dst[1], src + cp_raw[1]);
}

// ---------------------------------------------------------------------------
// one k16 block (KB) of chunk C: all schedule data compile-time.
// ab[mb][jo][0,1] = bf16x2 of x rows (wm+16mb+g, +8) at j = 8jo + 2*t4.
// xqg points at this thread's scale quadruple base; j-stride 128 u32.
// ---------------------------------------------------------------------------
template<int C, int KB>
__device__ __forceinline__ void do_kb(uint32_t bb, const uint32_t (&boff)[8],
    const uint32_t (&ab)[2][8][2], const uint32_t* __restrict__ xqg,
    float (&acc)[2][4][4])
{
    constexpr HD H0 = half_desc(C * 8 + KB * 2);
    constexpr HD H1 = half_desc(C * 8 + KB * 2 + 1);
    uint32_t sv0[4], sv1[4];
    if constexpr (H0.i == 64) {
        sv0[0] = sv0[1] = sv0[2] = sv0[3] = 0x3F803F80u;    // bf16x2(1,1)
    } else {
        uint4 s = *reinterpret_cast<const uint4*>(xqg + H0.i * 128);
        sv0[0] = s.x; sv0[1] = s.y; sv0[2] = s.z; sv0[3] = s.w;
    }
    if constexpr (H1.i == H0.i) {
        sv1[0] = sv0[0]; sv1[1] = sv0[1]; sv1[2] = sv0[2]; sv1[3] = sv0[3];
    } else if constexpr (H1.i == 64) {
        sv1[0] = sv1[1] = sv1[2] = sv1[3] = 0x3F803F80u;
    } else {
        uint4 s = *reinterpret_cast<const uint4*>(xqg + H1.i * 128);
        sv1[0] = s.x; sv1[1] = s.y; sv1[2] = s.z; sv1[3] = s.w;
    }
    uint32_t bf[4][2];
    LDSM_X4(bf[0][0], bf[0][1], bf[1][0], bf[1][1], bb + boff[KB * 2 + 0]);
    LDSM_X4(bf[2][0], bf[2][1], bf[3][0], bf[3][1], bb + boff[KB * 2 + 1]);
    #pragma unroll
    for (int mb = 0; mb < 2; mb++) {
        uint32_t t0, t1, t2, t3;
        HMUL2(t0, ab[mb][H0.jo][0], sv0[2 * mb]);      // rows g,   k 0-7
        HMUL2(t1, ab[mb][H0.jo][1], sv0[2 * mb + 1]);  // rows g+8, k 0-7
        HMUL2(t2, ab[mb][H1.jo][0], sv1[2 * mb]);      // rows g,   k 8-15
        HMUL2(t3, ab[mb][H1.jo][1], sv1[2 * mb + 1]);  // rows g+8, k 8-15
        #pragma unroll
        for (int nb = 0; nb < 4; nb++)
            MMA16816(acc[mb][nb], t0, t1, t2, t3, bf[nb][0], bf[nb][1]);
    }
}

// ---------------------------------------------------------------------------
// chunk recursion: quad step (barrier + prefetch + wait) every 4th chunk.
// ---------------------------------------------------------------------------
template<int C>
__device__ __forceinline__ void run_chunks(
    uint32_t sb, const uint32_t (&boff)[8], const uint32_t (&ab)[2][8][2],
    const uint32_t* __restrict__ xqg, float (&acc)[2][4][4],
    const uint32_t (&cp_raw)[2], const uint32_t (&cp_dst)[2])
{
    if constexpr (C < kChunks) {
        if constexpr ((C & 3) == 0) {
            __syncthreads();            // buffers of chunks C-4..C-1 reusable
            #pragma unroll
            for (int q = 0; q < 4; q++) {   // exactly 4 commits per quad
                if (C + 4 + q < kChunks)
                    issue_chunk(C + 4 + q, sb, cp_raw, cp_dst);
                CP_COMMIT();
            }
            CP_WAIT4();                 // chunks C..C+3 landed
        }
        uint32_t bb = sb + SM_B + (uint32_t)(C & 7) * kChunkBytes;
        do_kb<C, 0>(bb, boff, ab, xqg, acc);
        do_kb<C, 1>(bb, boff, ab, xqg, acc);
        do_kb<C, 2>(bb, boff, ab, xqg, acc);
        do_kb<C, 3>(bb, boff, ab, xqg, acc);
        run_chunks<C + 1>(sb, boff, ab, xqg, acc, cp_raw, cp_dst);
    }
}

// ---------------------------------------------------------------------------
// main fused kernel: 128-row M-tile per CTA, H=128 as N, 16 warps (4M x 4N),
// 1 CTA per SM, 8 B-buffers, barrier every 4 chunks
// ---------------------------------------------------------------------------
__global__ void __launch_bounds__(kThreads, 1)
rbm_main_kernel(const float* __restrict__ x,
                const float* __restrict__ bias,
                float* __restrict__ out) {
    extern __shared__ char smem_raw[];
    char* sm = (char*)((((uintptr_t)smem_raw) + 1023) & ~(uintptr_t)1023);
    const uint32_t sb = smem_u32(sm);
    const int tid = threadIdx.x;
    const int l   = tid & 31;
    const int w   = tid >> 5;
    const int g   = l >> 2;
    const int t4  = l & 3;
    const int wm  = (w >> 2) * 32;     // warp M offset (0,32,64,96)
    const int wn  = (w & 3) * 32;      // warp N offset (0,32,64,96)
    const int m0  = blockIdx.x * kMTile;

    float*    sbias = (float*)(sm + SM_BIAS);
    float*    spart = (float*)(sm + SM_PART);     // [m][4 wn-groups]
    uint32_t* xq    = (uint32_t*)(sm + SM_XQ);    // [j][32 grp][4 t] u32

    if (tid < kH) sbias[tid] = bias[tid];

    // --- x bf16 tile [m][j], 128B rows, SW128 swizzled (A ldmatrix source);
    //     lives in buffer-4 space, consumed before the first quad barrier ---
    {
        const float4* x4 = (const float4*)(x + (size_t)m0 * kV);
        #pragma unroll
        for (int e = tid; e < kMTile * 16; e += kThreads) {   // 128 rows * 16 f4
            int r = e >> 4, q = e & 15;
            float4 f = x4[e];
            uint32_t u0, u1;
            CVT_BF16X2(u0, f.x, f.y);
            CVT_BF16X2(u1, f.z, f.w);
            uint32_t off = (uint32_t)(r * 128 + q * 8);
            *(uint2*)(sm + SM_XT + SW128(off)) = make_uint2(u0, u1);
        }
    }
    // --- xq[j][grp][t] = bf16x2 broadcast of x[m0 + (grp>>3)*32 + (grp&7) + 8t][j]
    #pragma unroll
    for (int e = tid; e < kV * 32 * 4; e += kThreads) {   // 8192 entries
        int j   = e >> 7;
        int grp = (e >> 2) & 31;
        int t   = e & 3;
        int m   = (grp >> 3) * 32 + (grp & 7) + 8 * t;
        float v = x[(size_t)(m0 + m) * kV + j];
        uint32_t p;
        CVT_BF16X2(p, v, v);
        xq[e] = p;
    }

    // --- cp.async offsets (hoisted): 2 x 16B per thread per chunk ---
    uint32_t cp_raw[2], cp_dst[2];
    #pragma unroll
    for (int p = 0; p < 2; p++) {
        int cg = tid + p * kThreads;
        cp_raw[p] = (uint32_t)((cg >> 3) * 128 + (cg & 7) * 16);
        cp_dst[p] = SW128(cp_raw[p]);
    }

    // prologue: chunks 0..3 into buffers 0..3 (one commit each)
    #pragma unroll
    for (int p = 0; p < 4; p++) { issue_chunk(p, sb, cp_raw, cp_dst); CP_COMMIT(); }

    __syncthreads();   // x tiles + bias ready

    // --- A-base fragments (warp's 32x64 x-tile) in registers, octet-indexed:
    //     ab[mb][jo][0] = row wm+16mb+g,   ab[mb][jo][1] = row +8, octet jo ---
    uint32_t ab[2][8][2];
    {
        int q = l >> 3, rr = l & 7;
        #pragma unroll
        for (int mb = 0; mb < 2; mb++)
        #pragma unroll
        for (int kb = 0; kb < 4; kb++) {
            uint32_t off = (uint32_t)((wm + 16 * mb + (q & 1) * 8 + rr) * 128
                                      + (kb * 16 + (q >> 1) * 8) * 2);
            LDSM_X4(ab[mb][2 * kb][0], ab[mb][2 * kb][1],
                    ab[mb][2 * kb + 1][0], ab[mb][2 * kb + 1][1],
                    sb + SM_XT + SW128(off));
        }
    }

    // --- per-thread B ldmatrix offsets (swizzled, rel. to buffer base) ---
    uint32_t boff[8];
    {
        int q = l >> 3, rr = l & 7;
        #pragma unroll
        for (int kb = 0; kb < 4; kb++)
        #pragma unroll
        for (int nb2 = 0; nb2 < 2; nb2++) {
            uint32_t off = (uint32_t)((wn + nb2 * 16 + (q >> 1) * 8 + rr) * 128
                                      + (kb * 16 + (q & 1) * 8) * 2);
            boff[kb * 2 + nb2] = SW128(off);
        }
    }

    float acc[2][4][4];
    #pragma unroll
    for (int a = 0; a < 2; a++)
    #pragma unroll
    for (int b = 0; b < 4; b++)
    #pragma unroll
    for (int c = 0; c < 4; c++) acc[a][b][c] = 0.0f;

    const int rb0 = wm + g;
    const uint32_t* xqg = xq + ((wm >> 2) + g) * 4;   // grp = (wm>>2)+g

    run_chunks<0>(sb, boff, ab, xqg, acc, cp_raw, cp_dst);

    // --- epilogue: a = bias + 0.5*acc; psi = prod cos(a) ---
    #pragma unroll
    for (int mb = 0; mb < 2; mb++) {
        float p0 = 1.0f, p1 = 1.0f;
        #pragma unroll
        for (int nb = 0; nb < 4; nb++) {
            int col = wn + nb * 8 + 2 * t4;
            #pragma unroll
            for (int cc = 0; cc < 2; cc++) {
                float bv = sbias[col + cc];
                p0 *= cos_poly(bv + 0.5f * acc[mb][nb][cc]);       // row g
                p1 *= cos_poly(bv + 0.5f * acc[mb][nb][2 + cc]);   // row g+8
            }
        }
        p0 *= __shfl_xor_sync(0xFFFFFFFFu, p0, 1);
        p0 *= __shfl_xor_sync(0xFFFFFFFFu, p0, 2);
        p1 *= __shfl_xor_sync(0xFFFFFFFFu, p1, 1);
        p1 *= __shfl_xor_sync(0xFFFFFFFFu, p1, 2);
        if (t4 == 0) {
            spart[(rb0 + 16 * mb) * 4 + (w & 3)]     = p0;
            spart[(rb0 + 16 * mb + 8) * 4 + (w & 3)] = p1;
        }
    }
    __syncthreads();
    if (tid < kMTile) {
        out[m0 + tid] = spart[tid * 4 + 0] * spart[tid * 4 + 1]
                      * spart[tid * 4 + 2] * spart[tid * 4 + 3];
    }
}

// ---------------------------------------------------------------------------
// launch
// ---------------------------------------------------------------------------
extern "C" void kernel_launch(void* const* d_in, const int* in_sizes, int n_in,
                              void* d_out, int out_size) {
    const float* x    = (const float*)d_in[0];   // (16384, 64)
    const float* w1   = (const float*)d_in[1];   // (64, 128)
    const float* w2   = (const float*)d_in[2];   // (128, 64, 64)
    const float* bias = (const float*)d_in[3];   // (128,)
    float* out = (float*)d_out;                  // (16384,)

    cudaFuncSetAttribute(rbm_main_kernel,
                         cudaFuncAttributeMaxDynamicSharedMemorySize, SMEM_TOTAL);

    prep_kernel<<<kH, 256>>>(w2, w1);            // one CTA per h
    rbm_main_kernel<<<16384 / kMTile, kThreads, SMEM_TOTAL>>>(x, bias, out);
}

// round 11
// speedup vs baseline: 1.4286x; 1.0468x over previous
#include <cuda_runtime.h>
#include <cuda_bf16.h>
#include <cstdint>

// ============================================================================
// IsingRBM: psi[m] = prod_h cos(bias[h] + (x@W1)[m,h] + 0.5 * x^T W2[h] x)
// mma.sync.m16n8k16 bf16 (compute_103 baseline PTX; tcgen05 unavailable).
//
// R11: B operand pre-packed in MMA FRAGMENT ORDER -> direct LDG to registers.
//  * prep writes g_wb[c][W][kb][q][lane][16B]: exactly the fragment each
//    thread needs, so the main loop does 2 coalesced LDG.128 per kb and NO
//    smem staging for B at all: no cp.async, no LDSM, no wait_group, and
//    ZERO __syncthreads in the main loop (warps fully independent).
//  * register double-buffer at kb granularity: consume bfr[KB] (chunk C),
//    then LDG chunk C+1's KB into the same regs (~1 chunk of latency cover).
//  * 8-granular symmetric packing kept (K = 2368, 37 chunks); schedule from
//    the single constexpr half_desc used by both prep and main.
//  * skeleton otherwise R10: 512 thr, 1 CTA/SM, M-tile 128, 4Mx4N warps.
// ============================================================================

static constexpr int kV = 64;
static constexpr int kH = 128;
static constexpr int kMTile = 128;
static constexpr int kChunks = 37;
static constexpr int kChunkBytes = kH * kV * 2;   // 16384
static constexpr int kThreads = 512;

// smem layout (bytes, relative to 1024-aligned base) — no B buffers anymore
static constexpr int SM_BIAS = 0;                  // 128 f32 = 512
static constexpr int SM_PART = 512;                // 128*4 f32 = 2048
static constexpr int SM_XQ   = 2560;               // 64 j * 32 grp * 4 t u32 = 32768
static constexpr int SM_XT   = 36864;              // 1024-aligned, 16384
static constexpr int SM_END  = SM_XT + 16384;      // 53248
static constexpr int SMEM_TOTAL = SM_END + 1024;

// Fragment-ordered B operand: [c][W(4)][kb(4)][q(2)][lane(32)][16B]
__device__ __align__(16) unsigned char g_wb[kChunks * kChunkBytes];

// ---------------------------------------------------------------------------
// schedule: half H (octet of K) -> (row i, j-octet jo).  i == 64 => linear.
// ---------------------------------------------------------------------------
struct HD { int i; int jo; };
__host__ __device__ constexpr HD half_desc(int H) {
    if (H >= 288) return HD{64, H - 288};          // linear term (scale = 1)
    int a = 0, gs = 0;
    while (gs + 8 * (8 - a) <= H) { gs += 8 * (8 - a); ++a; }
    int rem = H - gs, len = 8 - a;
    return HD{8 * a + rem / len, a + rem % len};
}

// ---------------------------------------------------------------------------
// helpers
// ---------------------------------------------------------------------------
__device__ __forceinline__ uint32_t smem_u32(const void* p) {
    uint32_t a;
    asm("{ .reg .u64 t; cvta.to.shared.u64 t, %1; cvt.u32.u64 %0, t; }"
        : "=r"(a) : "l"(p));
    return a;
}

#define SW128(o) ((o) ^ (((o) >> 3) & 0x70))

#define CVT_BF16X2(result, a, b) \
    asm("cvt.rn.bf16x2.f32 %0, %1, %2;" : "=r"(result) : "f"(b), "f"(a))

#define HMUL2(d, a, b) \
    asm("mul.rn.bf16x2 %0, %1, %2;" : "=r"(d) : "r"(a), "r"(b))

#define LDSM_X4(r0, r1, r2, r3, addr) \
    asm volatile("ldmatrix.sync.aligned.m8n8.x4.shared.b16 {%0,%1,%2,%3}, [%4];" \
        : "=r"(r0), "=r"(r1), "=r"(r2), "=r"(r3) : "r"(addr))

#define MMA16816(d, a0, a1, a2, a3, b0, b1) \
    asm volatile("mma.sync.aligned.m16n8k16.row.col.f32.bf16.bf16.f32 " \
        "{%0,%1,%2,%3}, {%4,%5,%6,%7}, {%8,%9}, {%0,%1,%2,%3};" \
        : "+f"((d)[0]), "+f"((d)[1]), "+f"((d)[2]), "+f"((d)[3]) \
        : "r"(a0), "r"(a1), "r"(a2), "r"(a3), "r"(b0), "r"(b1))

__device__ __forceinline__ float cos_poly(float a) {
    // |a| < 0.1 guaranteed by problem statistics; deg-8 Taylor, err < 1e-12
    float t = a * a;
    return 1.0f + t * (-0.5f + t * (4.16666667e-2f +
               t * (-1.38888889e-3f + t * 2.48015873e-5f)));
}

// ---------------------------------------------------------------------------
// prep: one CTA per h. Stage W2[h] in smem (coalesced), emit the folded
// weights directly in per-thread fragment order.
// h -> W = h>>5 (warp n-group), nb = (h>>3)&3, lrow = h&7.
// Fragment element (c, kb, t in 0..3): lane = lrow*4+t holds k-pairs
// (2t,2t+1) [u32 p=0] and (2t+8,2t+9) [p=1] of column block kb.
// uint2 index = c*2048 + kb*128 + t*2 + [W*512 + (nb>>1)*64 + lrow*8 + (nb&1)]
// ---------------------------------------------------------------------------
__global__ void __launch_bounds__(256) prep_kernel(const float* __restrict__ w2,
                                                   const float* __restrict__ w1) {
    __shared__ float sw[4096];
    const int h = blockIdx.x;
    const float4* src = reinterpret_cast<const float4*>(w2 + (size_t)h * 4096);
    #pragma unroll
    for (int e = threadIdx.x; e < 1024; e += 256)
        reinterpret_cast<float4*>(sw)[e] = src[e];
    __syncthreads();

    const int W = h >> 5, nb = (h >> 3) & 3, lrow = h & 7;
    const int hbase = W * 512 + (nb >> 1) * 64 + lrow * 8 + (nb & 1);
    uint2* dst = reinterpret_cast<uint2*>(g_wb);

    // 37 chunks * 4 kb * 4 t = 592 uint2 outputs for this h
    for (int idx = threadIdx.x; idx < kChunks * 16; idx += 256) {
        int c  = idx >> 4;
        int r  = idx & 15;
        int kb = r >> 2;
        int t  = r & 3;
        float v[4];
        #pragma unroll
        for (int q = 0; q < 4; q++) {
            int klocal = (q < 2) ? (2 * t + q) : (2 * t + 6 + q);  // 2t,2t+1,2t+8,2t+9
            HD hd = half_desc(c * 8 + kb * 2 + (klocal >> 3));
            int j = hd.jo * 8 + (klocal & 7);
            if (hd.i == 64)     v[q] = 2.0f * w1[j * kH + h];
            else if (j > hd.i)  v[q] = sw[hd.i * 64 + j] + sw[j * 64 + hd.i];
            else if (j == hd.i) v[q] = sw[hd.i * 64 + j];
            else                v[q] = 0.0f;   // octet padding below diagonal
        }
        uint32_t lo, hi;
        CVT_BF16X2(lo, v[0], v[1]);   // lo half = even k
        CVT_BF16X2(hi, v[2], v[3]);
        dst[c * 2048 + kb * 128 + t * 2 + hbase] = make_uint2(lo, hi);
    }
}

// ---------------------------------------------------------------------------
// one k16 block (KB) of chunk C. Consumes bfr[KB] (fragments of chunk C),
// then prefetches chunk C+1's KB into the same registers.
// lo = {bf[0][0], bf[0][1], bf[1][0], bf[1][1]}, hi = nb 2,3.
// ---------------------------------------------------------------------------
template<int C, int KB>
__device__ __forceinline__ void do_kb(
    const uint4* __restrict__ gB, uint4 (&bfr)[4][2],
    const uint32_t (&ab)[2][8][2], const uint32_t* __restrict__ xqg,
    float (&acc)[2][4][4])
{
    constexpr HD H0 = half_desc(C * 8 + KB * 2);
    constexpr HD H1 = half_desc(C * 8 + KB * 2 + 1);
    uint32_t sv0[4], sv1[4];
    if constexpr (H0.i == 64) {
        sv0[0] = sv0[1] = sv0[2] = sv0[3] = 0x3F803F80u;    // bf16x2(1,1)
    } else {
        uint4 s = *reinterpret_cast<const uint4*>(xqg + H0.i * 128);
        sv0[0] = s.x; sv0[1] = s.y; sv0[2] = s.z; sv0[3] = s.w;
    }
    if constexpr (H1.i == H0.i) {
        sv1[0] = sv0[0]; sv1[1] = sv0[1]; sv1[2] = sv0[2]; sv1[3] = sv0[3];
    } else if constexpr (H1.i == 64) {
        sv1[0] = sv1[1] = sv1[2] = sv1[3] = 0x3F803F80u;
    } else {
        uint4 s = *reinterpret_cast<const uint4*>(xqg + H1.i * 128);
        sv1[0] = s.x; sv1[1] = s.y; sv1[2] = s.z; sv1[3] = s.w;
    }
    const uint4 lo = bfr[KB][0], hi = bfr[KB][1];
    if constexpr (C + 1 < kChunks) {   // prefetch next chunk's KB fragments
        bfr[KB][0] = gB[(C + 1) * 1024 + KB * 64];
        bfr[KB][1] = gB[(C + 1) * 1024 + KB * 64 + 32];
    }
    #pragma unroll
    for (int mb = 0; mb < 2; mb++) {
        uint32_t t0, t1, t2, t3;
        HMUL2(t0, ab[mb][H0.jo][0], sv0[2 * mb]);      // rows g,   k 0-7
        HMUL2(t1, ab[mb][H0.jo][1], sv0[2 * mb + 1]);  // rows g+8, k 0-7
        HMUL2(t2, ab[mb][H1.jo][0], sv1[2 * mb]);      // rows g,   k 8-15
        HMUL2(t3, ab[mb][H1.jo][1], sv1[2 * mb + 1]);  // rows g+8, k 8-15
        MMA16816(acc[mb][0], t0, t1, t2, t3, lo.x, lo.y);
        MMA16816(acc[mb][1], t0, t1, t2, t3, lo.z, lo.w);
        MMA16816(acc[mb][2], t0, t1, t2, t3, hi.x, hi.y);
        MMA16816(acc[mb][3], t0, t1, t2, t3, hi.z, hi.w);
    }
}

template<int C>
__device__ __forceinline__ void run_chunks(
    const uint4* __restrict__ gB, uint4 (&bfr)[4][2],
    const uint32_t (&ab)[2][8][2], const uint32_t* __restrict__ xqg,
    float (&acc)[2][4][4])
{
    if constexpr (C < kChunks) {
        do_kb<C, 0>(gB, bfr, ab, xqg, acc);
        do_kb<C, 1>(gB, bfr, ab, xqg, acc);
        do_kb<C, 2>(gB, bfr, ab, xqg, acc);
        do_kb<C, 3>(gB, bfr, ab, xqg, acc);
        run_chunks<C + 1>(gB, bfr, ab, xqg, acc);
    }
}

// ---------------------------------------------------------------------------
// main fused kernel: 128-row M-tile per CTA, H=128 as N, 16 warps (4M x 4N),
// 1 CTA per SM, NO barriers in the main loop
// ---------------------------------------------------------------------------
__global__ void __launch_bounds__(kThreads, 1)
rbm_main_kernel(const float* __restrict__ x,
                const float* __restrict__ bias,
                float* __restrict__ out) {
    extern __shared__ char smem_raw[];
    char* sm = (char*)((((uintptr_t)smem_raw) + 1023) & ~(uintptr_t)1023);
    const uint32_t sb = smem_u32(sm);
    const int tid = threadIdx.x;
    const int l   = tid & 31;
    const int w   = tid >> 5;
    const int g   = l >> 2;
    const int t4  = l & 3;
    const int wm  = (w >> 2) * 32;     // warp M offset (0,32,64,96)
    const int wn  = (w & 3) * 32;      // warp N offset (0,32,64,96)
    const int m0  = blockIdx.x * kMTile;

    float*    sbias = (float*)(sm + SM_BIAS);
    float*    spart = (float*)(sm + SM_PART);     // [m][4 wn-groups]
    uint32_t* xq    = (uint32_t*)(sm + SM_XQ);    // [j][32 grp][4 t] u32

    if (tid < kH) sbias[tid] = bias[tid];

    // --- x bf16 tile [m][j], 128B rows, SW128 swizzled (A ldmatrix source) ---
    {
        const float4* x4 = (const float4*)(x + (size_t)m0 * kV);
        #pragma unroll
        for (int e = tid; e < kMTile * 16; e += kThreads) {   // 128 rows * 16 f4
            int r = e >> 4, q = e & 15;
            float4 f = x4[e];
            uint32_t u0, u1;
            CVT_BF16X2(u0, f.x, f.y);
            CVT_BF16X2(u1, f.z, f.w);
            uint32_t off = (uint32_t)(r * 128 + q * 8);
            *(uint2*)(sm + SM_XT + SW128(off)) = make_uint2(u0, u1);
        }
    }
    // --- xq[j][grp][t] = bf16x2 broadcast of x[m0 + (grp>>3)*32 + (grp&7) + 8t][j]
    #pragma unroll
    for (int e = tid; e < kV * 32 * 4; e += kThreads) {   // 8192 entries
        int j   = e >> 7;
        int grp = (e >> 2) & 31;
        int t   = e & 3;
        int m   = (grp >> 3) * 32 + (grp & 7) + 8 * t;
        float v = x[(size_t)(m0 + m) * kV + j];
        uint32_t p;
        CVT_BF16X2(p, v, v);
        xq[e] = p;
    }

    // --- per-thread fragment pointer into g_wb (uint4 units) ---
    const uint4* gB = reinterpret_cast<const uint4*>(g_wb) + (w & 3) * 256 + l;

    // --- prologue: chunk 0 fragments into registers ---
    uint4 bfr[4][2];
    #pragma unroll
    for (int kb = 0; kb < 4; kb++) {
        bfr[kb][0] = gB[kb * 64];
        bfr[kb][1] = gB[kb * 64 + 32];
    }

    __syncthreads();   // x tiles + bias ready (only barrier before epilogue)

    // --- A-base fragments (warp's 32x64 x-tile) in registers, octet-indexed ---
    uint32_t ab[2][8][2];
    {
        int q = l >> 3, rr = l & 7;
        #pragma unroll
        for (int mb = 0; mb < 2; mb++)
        #pragma unroll
        for (int kb = 0; kb < 4; kb++) {
            uint32_t off = (uint32_t)((wm + 16 * mb + (q & 1) * 8 + rr) * 128
                                      + (kb * 16 + (q >> 1) * 8) * 2);
            LDSM_X4(ab[mb][2 * kb][0], ab[mb][2 * kb][1],
                    ab[mb][2 * kb + 1][0], ab[mb][2 * kb + 1][1],
                    sb + SM_XT + SW128(off));
        }
    }

    float acc[2][4][4];
    #pragma unroll
    for (int a = 0; a < 2; a++)
    #pragma unroll
    for (int b = 0; b < 4; b++)
    #pragma unroll
    for (int c = 0; c < 4; c++) acc[a][b][c] = 0.0f;

    const int rb0 = wm + g;
    const uint32_t* xqg = xq + ((wm >> 2) + g) * 4;   // grp = (wm>>2)+g

    run_chunks<0>(gB, bfr, ab, xqg, acc);

    // --- epilogue: a = bias + 0.5*acc; psi = prod cos(a) ---
    #pragma unroll
    for (int mb = 0; mb < 2; mb++) {
        float p0 = 1.0f, p1 = 1.0f;
        #pragma unroll
        for (int nb = 0; nb < 4; nb++) {
            int col = wn + nb * 8 + 2 * t4;
            #pragma unroll
            for (int cc = 0; cc < 2; cc++) {
                float bv = sbias[col + cc];
                p0 *= cos_poly(bv + 0.5f * acc[mb][nb][cc]);       // row g
                p1 *= cos_poly(bv + 0.5f * acc[mb][nb][2 + cc]);   // row g+8
            }
        }
        p0 *= __shfl_xor_sync(0xFFFFFFFFu, p0, 1);
        p0 *= __shfl_xor_sync(0xFFFFFFFFu, p0, 2);
        p1 *= __shfl_xor_sync(0xFFFFFFFFu, p1, 1);
        p1 *= __shfl_xor_sync(0xFFFFFFFFu, p1, 2);
        if (t4 == 0) {
            spart[(rb0 + 16 * mb) * 4 + (w & 3)]     = p0;
            spart[(rb0 + 16 * mb + 8) * 4 + (w & 3)] = p1;
        }
    }
    __syncthreads();
    if (tid < kMTile) {
        out[m0 + tid] = spart[tid * 4 + 0] * spart[tid * 4 + 1]
                      * spart[tid * 4 + 2] * spart[tid * 4 + 3];
    }
}

// ---------------------------------------------------------------------------
// launch
// ---------------------------------------------------------------------------
extern "C" void kernel_launch(void* const* d_in, const int* in_sizes, int n_in,
                              void* d_out, int out_size) {
    const float* x    = (const float*)d_in[0];   // (16384, 64)
    const float* w1   = (const float*)d_in[1];   // (64, 128)
    const float* w2   = (const float*)d_in[2];   // (128, 64, 64)
    const float* bias = (const float*)d_in[3];   // (128,)
    float* out = (float*)d_out;                  // (16384,)

    cudaFuncSetAttribute(rbm_main_kernel,
                         cudaFuncAttributeMaxDynamicSharedMemorySize, SMEM_TOTAL);

    prep_kernel<<<kH, 256>>>(w2, w1);            // one CTA per h
    rbm_main_kernel<<<16384 / kMTile, kThreads, SMEM_TOTAL>>>(x, bias, out);
}